// round 16
// baseline (speedup 1.0000x reference)
#include <cuda_runtime.h>
#include <cuda_bf16.h>
#include <cstdint>

// Problem constants (fixed shapes)
#define L_TOK   4096
#define D_HID   768
#define H_HEAD  12
#define DH      64
#define M2      2048          // L/2
#define OUT_TOK 2049          // 1 unmerged + 2048 dst

// ---------------- device scratch (no allocations allowed) ----------------
__device__ float              g_m[L_TOK * DH];      // normalized metric, 1 MB
__device__ unsigned long long g_best[M2];           // packed (score, ~col)
__device__ int                g_cnt[M2];            // #srcs per dst
__device__ int                g_off[M2];            // CSR offsets
__device__ int                g_list[M2];           // src rows grouped by dst

__device__ __forceinline__ unsigned sortable_f32(float f) {
    unsigned u = __float_as_uint(f);
    return (u & 0x80000000u) ? ~u : (u | 0x80000000u);
}
__device__ __forceinline__ unsigned long long pack2(float x) {
    unsigned long long r;
    asm("mov.b64 %0, {%1, %1};" : "=l"(r) : "f"(x));
    return r;
}
__device__ __forceinline__ void ffma2(unsigned long long& d,
                                      unsigned long long a,
                                      unsigned long long b) {
    asm("fma.rn.f32x2 %0, %1, %2, %0;" : "+l"(d) : "l"(a), "l"(b));
}

// ------------------------------------------------------------------------
// K1: metric = mean over heads of key_layer[0], L2-normalized per row.
// 2 warps per row (6 heads each), float2 loads. 8 rows per 512-thread block.
// grid: 512 x 512.  Also initializes g_best.
// ------------------------------------------------------------------------
__global__ __launch_bounds__(512) void k_metric(const float* __restrict__ key) {
    __shared__ float2 s_part[8][32];   // partial sums from odd-half warps

    int gtid = blockIdx.x * blockDim.x + threadIdx.x;
    if (gtid < M2 * 8 && (gtid & 7) == 0) g_best[gtid >> 3] = 0ull;

    int t    = threadIdx.x;
    int pair = t >> 6;                 // 0..7 : row slot in block
    int half = (t >> 5) & 1;           // 0: heads 0-5, 1: heads 6-11
    int lane = t & 31;
    int row  = blockIdx.x * 8 + pair;  // 0..4095

    const float2* base = (const float2*)(key + (size_t)row * DH) + lane;
    const size_t hstride = (size_t)L_TOK * DH / 2;    // head stride in float2

    float2 v = make_float2(0.f, 0.f);
    #pragma unroll
    for (int h = 0; h < 6; h++) {
        float2 x = base[(size_t)(half * 6 + h) * hstride];
        v.x += x.x; v.y += x.y;
    }

    if (half == 1) s_part[pair][lane] = v;
    __syncthreads();

    if (half == 0) {
        float2 o = s_part[pair][lane];
        v.x += o.x; v.y += o.y;
        const float invH = 1.0f / (float)H_HEAD;
        v.x *= invH; v.y *= invH;
        float ss = v.x * v.x + v.y * v.y;
        #pragma unroll
        for (int o2 = 16; o2; o2 >>= 1) ss += __shfl_xor_sync(0xffffffffu, ss, o2);
        float r = rsqrtf(ss);
        r = r * (1.5f - 0.5f * ss * r * r);   // one Newton step
        v.x *= r; v.y *= r;
        ((float2*)(g_m + row * DH))[lane] = v;
    }
}

// ------------------------------------------------------------------------
// K2: argmax_j dot(a_i, b_j) — 2048x2048x64 fp32 GEMM with FFMA2.
// Tile 64x64, 64 threads, 8x8 microtile, 32 KB static smem.
// 1024 CTAs (32x32) -> ~7 CTAs/SM, near-perfect single-wave balance.
// ------------------------------------------------------------------------
__global__ __launch_bounds__(64) void k_argmax() {
    __shared__ float As[64 * 64];   // K-major: As[k*64 + m]
    __shared__ float Bs[64 * 64];

    int t  = threadIdx.x;           // 0..63
    int tx = t & 7;                 // col group (8 cols each)
    int ty = t >> 3;                // row group (8 rows each)

    int aRow0 = blockIdx.y * 64;
    int bRow0 = blockIdx.x * 64;

    // Load: thread t owns a-row (aRow0+t) and b-row (bRow0+t); transpose to K-major.
    {
        const float4* arow = (const float4*)&g_m[(size_t)(2 * (aRow0 + t)) * DH];
        const float4* brow = (const float4*)&g_m[(size_t)(2 * (bRow0 + t) + 1) * DH];
        #pragma unroll
        for (int q = 0; q < 16; q++) {
            float4 va = arow[q];
            float4 vb = brow[q];
            As[(4 * q + 0) * 64 + t] = va.x;
            As[(4 * q + 1) * 64 + t] = va.y;
            As[(4 * q + 2) * 64 + t] = va.z;
            As[(4 * q + 3) * 64 + t] = va.w;
            Bs[(4 * q + 0) * 64 + t] = vb.x;
            Bs[(4 * q + 1) * 64 + t] = vb.y;
            Bs[(4 * q + 2) * 64 + t] = vb.z;
            Bs[(4 * q + 3) * 64 + t] = vb.w;
        }
    }
    __syncthreads();

    unsigned long long acc2[8][4];
    #pragma unroll
    for (int r = 0; r < 8; r++)
        #pragma unroll
        for (int c = 0; c < 4; c++) acc2[r][c] = 0ull;

    #pragma unroll 8
    for (int k = 0; k < 64; k++) {
        float4 a0 = *(const float4*)&As[k * 64 + ty * 8];
        float4 a1 = *(const float4*)&As[k * 64 + ty * 8 + 4];
        ulonglong2 b01 = *(const ulonglong2*)&Bs[k * 64 + tx * 8];      // (b0,b1),(b2,b3)
        ulonglong2 b23 = *(const ulonglong2*)&Bs[k * 64 + tx * 8 + 4];  // (b4,b5),(b6,b7)
        unsigned long long ap[8];
        ap[0] = pack2(a0.x); ap[1] = pack2(a0.y);
        ap[2] = pack2(a0.z); ap[3] = pack2(a0.w);
        ap[4] = pack2(a1.x); ap[5] = pack2(a1.y);
        ap[6] = pack2(a1.z); ap[7] = pack2(a1.w);
        #pragma unroll
        for (int r = 0; r < 8; r++) {
            ffma2(acc2[r][0], ap[r], b01.x);
            ffma2(acc2[r][1], ap[r], b01.y);
            ffma2(acc2[r][2], ap[r], b23.x);
            ffma2(acc2[r][3], ap[r], b23.y);
        }
    }

    // Argmax epilogue: per a-row, reduce across the 8 tx threads
    #pragma unroll
    for (int r = 0; r < 8; r++) {
        int row = aRow0 + ty * 8 + r;
        unsigned long long key = 0ull;
        #pragma unroll
        for (int c2 = 0; c2 < 4; c2++) {
            unsigned lo, hi;
            asm("mov.b64 {%0, %1}, %2;" : "=r"(lo), "=r"(hi) : "l"(acc2[r][c2]));
            float s0 = __uint_as_float(lo), s1 = __uint_as_float(hi);
            int col0 = bRow0 + tx * 8 + 2 * c2;
            unsigned long long k0 =
                ((unsigned long long)sortable_f32(s0) << 32) | (unsigned)(~(unsigned)col0);
            unsigned long long k1 =
                ((unsigned long long)sortable_f32(s1) << 32) | (unsigned)(~(unsigned)(col0 + 1));
            if (k0 > key) key = k0;
            if (k1 > key) key = k1;
        }
        #pragma unroll
        for (int o = 4; o; o >>= 1) {
            unsigned long long other = __shfl_down_sync(0xffffffffu, key, o, 8);
            key = (other > key) ? other : key;
        }
        if (tx == 0) atomicMax(&g_best[row], key);
    }
}

// ------------------------------------------------------------------------
// K3: build CSR (counts, offsets, src lists) + the output pieces that
// don't depend on the merge (row 0 copy, attention mask, tome[0]).
// 1 block x 1024 threads, warp-shuffle scan.
// ------------------------------------------------------------------------
__global__ __launch_bounds__(1024) void k_build(const float* __restrict__ hidden,
                                                const float* __restrict__ tome,
                                                float* __restrict__ out) {
    __shared__ int s_cnt[M2];
    __shared__ int s_off[M2];
    __shared__ int s_wsum[32];
    int t    = threadIdx.x;
    int lane = t & 31;
    int wid  = t >> 5;
    int i0 = 2 * t, i1 = 2 * t + 1;

    // independent output pieces (overlap with scan latency)
    float* out_mask = out + (size_t)OUT_TOK * D_HID;
    float* out_tome = out_mask + OUT_TOK;
    if (t < 192) ((float4*)out)[t] = ((const float4*)hidden)[t];   // row 0
    for (int i = t; i < OUT_TOK; i += 1024) out_mask[i] = 0.0f;
    if (t == 0) out_tome[0] = tome[0];

    s_cnt[i0] = 0; s_cnt[i1] = 0;
    __syncthreads();

    int dA = (int)(~(unsigned)g_best[i0]) & (M2 - 1);
    int dB = (int)(~(unsigned)g_best[i1]) & (M2 - 1);
    if (i0 >= 1) atomicAdd(&s_cnt[dA], 1);   // src row 0 is unmerged
    atomicAdd(&s_cnt[dB], 1);
    __syncthreads();

    int a = s_cnt[i0], b = s_cnt[i1];
    int pair = a + b;

    int v = pair;                            // inclusive warp scan
    #pragma unroll
    for (int o = 1; o < 32; o <<= 1) {
        int n = __shfl_up_sync(0xffffffffu, v, o);
        if (lane >= o) v += n;
    }
    if (lane == 31) s_wsum[wid] = v;
    __syncthreads();
    if (wid == 0) {
        int w = s_wsum[lane];
        #pragma unroll
        for (int o = 1; o < 32; o <<= 1) {
            int n = __shfl_up_sync(0xffffffffu, w, o);
            if (lane >= o) w += n;
        }
        s_wsum[lane] = w;
    }
    __syncthreads();
    int incl = v + ((wid > 0) ? s_wsum[wid - 1] : 0);
    int excl = incl - pair;

    s_off[i0] = excl;
    s_off[i1] = excl + a;
    g_cnt[i0] = a;  g_cnt[i1] = b;
    g_off[i0] = excl; g_off[i1] = excl + a;
    __syncthreads();

    s_cnt[i0] = s_off[i0]; s_cnt[i1] = s_off[i1];   // fill cursors
    __syncthreads();
    if (i0 >= 1) { int p = atomicAdd(&s_cnt[dA], 1); g_list[p] = i0; }
    {             int p = atomicAdd(&s_cnt[dB], 1); g_list[p] = i1; }
}

// ------------------------------------------------------------------------
// K4: gather-merge (best-measured design), uniform grid.
// Block j: out row 1+j = (dst_row + sum srcs)/(1+cnt).   grid: 2048 x 192
// ------------------------------------------------------------------------
__global__ __launch_bounds__(192) void k_merge(const float* __restrict__ hidden,
                                               const float* __restrict__ tome,
                                               float* __restrict__ out) {
    float* out_tok  = out;                              // 2049 x 768
    float* out_tome = out + (size_t)OUT_TOK * D_HID + OUT_TOK;
    int j = blockIdx.x, t = threadIdx.x;

    int cnt = g_cnt[j];
    int off = g_off[j];
    float inv = 1.0f / (1.0f + (float)cnt);

    float4 acc = ((const float4*)&hidden[(size_t)(2 * j + 1) * D_HID])[t];

    int s = 0;
    for (; s + 4 <= cnt; s += 4) {
        int i0 = g_list[off + s + 0];
        int i1 = g_list[off + s + 1];
        int i2 = g_list[off + s + 2];
        int i3 = g_list[off + s + 3];
        float4 v0 = ((const float4*)&hidden[(size_t)(2 * i0) * D_HID])[t];
        float4 v1 = ((const float4*)&hidden[(size_t)(2 * i1) * D_HID])[t];
        float4 v2 = ((const float4*)&hidden[(size_t)(2 * i2) * D_HID])[t];
        float4 v3 = ((const float4*)&hidden[(size_t)(2 * i3) * D_HID])[t];
        acc.x += v0.x + v1.x + v2.x + v3.x;
        acc.y += v0.y + v1.y + v2.y + v3.y;
        acc.z += v0.z + v1.z + v2.z + v3.z;
        acc.w += v0.w + v1.w + v2.w + v3.w;
    }
    for (; s < cnt; s++) {
        int i0 = g_list[off + s];
        float4 v0 = ((const float4*)&hidden[(size_t)(2 * i0) * D_HID])[t];
        acc.x += v0.x; acc.y += v0.y; acc.z += v0.z; acc.w += v0.w;
    }
    acc.x *= inv; acc.y *= inv; acc.z *= inv; acc.w *= inv;
    ((float4*)&out_tok[(size_t)(1 + j) * D_HID])[t] = acc;

    if (t == 0) {
        float ts = tome[2 * j + 1];
        for (int q = 0; q < cnt; q++) ts += tome[2 * g_list[off + q]];
        out_tome[1 + j] = ts;
    }
}

// ------------------------------------------------------------------------
extern "C" void kernel_launch(void* const* d_in, const int* in_sizes, int n_in,
                              void* d_out, int out_size) {
    const float* hidden = (const float*)d_in[0];
    const float* key    = (const float*)d_in[3];
    const float* tome   = (const float*)d_in[4];
    float* out = (float*)d_out;

    k_metric<<<512, 512>>>(key);
    k_argmax<<<dim3(32, 32), 64>>>();
    k_build<<<1, 1024>>>(hidden, tome, out);
    k_merge<<<M2, 192>>>(hidden, tome, out);
}

// round 17
// speedup vs baseline: 1.2353x; 1.2353x over previous
#include <cuda_runtime.h>
#include <cuda_bf16.h>
#include <cstdint>

// Problem constants (fixed shapes)
#define L_TOK   4096
#define D_HID   768
#define H_HEAD  12
#define DH      64
#define M2      2048          // L/2
#define OUT_TOK 2049          // 1 unmerged + 2048 dst

// ---------------- device scratch (no allocations allowed) ----------------
__device__ float              g_m[L_TOK * DH];      // normalized metric, 1 MB
__device__ unsigned long long g_best[M2];           // packed (score, ~col)
__device__ int                g_cnt[M2];            // #srcs per dst
__device__ int                g_off[M2];            // CSR offsets
__device__ int                g_list[M2];           // src rows grouped by dst

__device__ __forceinline__ unsigned sortable_f32(float f) {
    unsigned u = __float_as_uint(f);
    return (u & 0x80000000u) ? ~u : (u | 0x80000000u);
}
__device__ __forceinline__ unsigned long long pack2(float x) {
    unsigned long long r;
    asm("mov.b64 %0, {%1, %1};" : "=l"(r) : "f"(x));
    return r;
}
__device__ __forceinline__ void ffma2(unsigned long long& d,
                                      unsigned long long a,
                                      unsigned long long b) {
    asm("fma.rn.f32x2 %0, %1, %2, %0;" : "+l"(d) : "l"(a), "l"(b));
}

// ------------------------------------------------------------------------
// K1: metric = mean over heads of key_layer[0], L2-normalized per row.
// 2 warps per row (6 heads each), float2 loads. 8 rows per 512-thread block.
// grid: 512 x 512.  Also initializes g_best.
// ------------------------------------------------------------------------
__global__ __launch_bounds__(512) void k_metric(const float* __restrict__ key) {
    __shared__ float2 s_part[8][32];   // partial sums from odd-half warps

    int gtid = blockIdx.x * blockDim.x + threadIdx.x;
    if (gtid < M2 * 8 && (gtid & 7) == 0) g_best[gtid >> 3] = 0ull;

    int t    = threadIdx.x;
    int pair = t >> 6;                 // 0..7 : row slot in block
    int half = (t >> 5) & 1;           // 0: heads 0-5, 1: heads 6-11
    int lane = t & 31;
    int row  = blockIdx.x * 8 + pair;  // 0..4095

    const float2* base = (const float2*)(key + (size_t)row * DH) + lane;
    const size_t hstride = (size_t)L_TOK * DH / 2;    // head stride in float2

    float2 v = make_float2(0.f, 0.f);
    #pragma unroll
    for (int h = 0; h < 6; h++) {
        float2 x = base[(size_t)(half * 6 + h) * hstride];
        v.x += x.x; v.y += x.y;
    }

    if (half == 1) s_part[pair][lane] = v;
    __syncthreads();

    if (half == 0) {
        float2 o = s_part[pair][lane];
        v.x += o.x; v.y += o.y;
        const float invH = 1.0f / (float)H_HEAD;
        v.x *= invH; v.y *= invH;
        float ss = v.x * v.x + v.y * v.y;
        #pragma unroll
        for (int o2 = 16; o2; o2 >>= 1) ss += __shfl_xor_sync(0xffffffffu, ss, o2);
        float r = rsqrtf(ss);
        r = r * (1.5f - 0.5f * ss * r * r);   // one Newton step
        v.x *= r; v.y *= r;
        ((float2*)(g_m + row * DH))[lane] = v;
    }
}

// ------------------------------------------------------------------------
// K2: argmax_j dot(a_i, b_j) — 2048x2048x64 fp32 GEMM with FFMA2.
// Tile 128x128, 256 threads, 8x8 microtile (proven best shape).
// A duplicated into (a,a) pairs in REGISTERS; B pairs reinterpreted from
// contiguous smem float4.  64 KB dynamic smem.  grid: (16, 16)
// ------------------------------------------------------------------------
#define BM 128
__global__ __launch_bounds__(256) void k_argmax() {
    extern __shared__ float smem[];
    float* As = smem;              // [64][128] K-major: As[k*128 + m]
    float* Bs = smem + 64 * BM;    // [64][128]

    int tid = threadIdx.x;
    int tx  = tid & 15;            // col group (8 cols each)
    int ty  = tid >> 4;            // row group (8 rows each)

    int aRow0 = blockIdx.y * BM;
    int bRow0 = blockIdx.x * BM;

    // Load tiles, transposing to K-major. 8 float4 per thread per matrix.
    int lm  = tid & 31;            // m within 32-row group
    int kq8 = tid >> 5;            // 0..7
    #pragma unroll
    for (int it = 0; it < 4; it++) {
        int m = it * 32 + lm;
        const float* arow = &g_m[(size_t)(2 * (aRow0 + m)) * DH];
        const float* brow = &g_m[(size_t)(2 * (bRow0 + m) + 1) * DH];
        #pragma unroll
        for (int half = 0; half < 2; half++) {
            int kq = kq8 + half * 8;           // 0..15
            float4 va = *(const float4*)&arow[kq * 4];
            float4 vb = *(const float4*)&brow[kq * 4];
            As[(kq * 4 + 0) * BM + m] = va.x;
            As[(kq * 4 + 1) * BM + m] = va.y;
            As[(kq * 4 + 2) * BM + m] = va.z;
            As[(kq * 4 + 3) * BM + m] = va.w;
            Bs[(kq * 4 + 0) * BM + m] = vb.x;
            Bs[(kq * 4 + 1) * BM + m] = vb.y;
            Bs[(kq * 4 + 2) * BM + m] = vb.z;
            Bs[(kq * 4 + 3) * BM + m] = vb.w;
        }
    }
    __syncthreads();

    unsigned long long acc2[8][4];
    #pragma unroll
    for (int r = 0; r < 8; r++)
        #pragma unroll
        for (int c = 0; c < 4; c++) acc2[r][c] = 0ull;

    #pragma unroll 8
    for (int k = 0; k < 64; k++) {
        float4 a0 = *(const float4*)&As[k * BM + ty * 8];
        float4 a1 = *(const float4*)&As[k * BM + ty * 8 + 4];
        ulonglong2 b01 = *(const ulonglong2*)&Bs[k * BM + tx * 8];      // (b0,b1),(b2,b3)
        ulonglong2 b23 = *(const ulonglong2*)&Bs[k * BM + tx * 8 + 4];  // (b4,b5),(b6,b7)
        unsigned long long ap[8];
        ap[0] = pack2(a0.x); ap[1] = pack2(a0.y);
        ap[2] = pack2(a0.z); ap[3] = pack2(a0.w);
        ap[4] = pack2(a1.x); ap[5] = pack2(a1.y);
        ap[6] = pack2(a1.z); ap[7] = pack2(a1.w);
        #pragma unroll
        for (int r = 0; r < 8; r++) {
            ffma2(acc2[r][0], ap[r], b01.x);
            ffma2(acc2[r][1], ap[r], b01.y);
            ffma2(acc2[r][2], ap[r], b23.x);
            ffma2(acc2[r][3], ap[r], b23.y);
        }
    }

    // Argmax epilogue: per a-row, reduce across the 16 tx threads (half-warp)
    #pragma unroll
    for (int r = 0; r < 8; r++) {
        int row = aRow0 + ty * 8 + r;
        unsigned long long key = 0ull;
        #pragma unroll
        for (int c2 = 0; c2 < 4; c2++) {
            unsigned lo, hi;
            asm("mov.b64 {%0, %1}, %2;" : "=r"(lo), "=r"(hi) : "l"(acc2[r][c2]));
            float s0 = __uint_as_float(lo), s1 = __uint_as_float(hi);
            int col0 = bRow0 + tx * 8 + 2 * c2;
            unsigned long long k0 =
                ((unsigned long long)sortable_f32(s0) << 32) | (unsigned)(~(unsigned)col0);
            unsigned long long k1 =
                ((unsigned long long)sortable_f32(s1) << 32) | (unsigned)(~(unsigned)(col0 + 1));
            if (k0 > key) key = k0;
            if (k1 > key) key = k1;
        }
        #pragma unroll
        for (int o = 8; o; o >>= 1) {
            unsigned long long other = __shfl_down_sync(0xffffffffu, key, o, 16);
            key = (other > key) ? other : key;
        }
        if (tx == 0) atomicMax(&g_best[row], key);
    }
}

// ------------------------------------------------------------------------
// K3: build CSR (counts, offsets, src lists) + merge-independent output
// pieces (row 0 copy, attention mask, tome[0]).
// 1 block x 1024 threads, warp-shuffle scan.
// ------------------------------------------------------------------------
__global__ __launch_bounds__(1024) void k_build(const float* __restrict__ hidden,
                                                const float* __restrict__ tome,
                                                float* __restrict__ out) {
    __shared__ int s_cnt[M2];
    __shared__ int s_off[M2];
    __shared__ int s_wsum[32];
    int t    = threadIdx.x;
    int lane = t & 31;
    int wid  = t >> 5;
    int i0 = 2 * t, i1 = 2 * t + 1;

    // independent output pieces (overlap with scan latency)
    float* out_mask = out + (size_t)OUT_TOK * D_HID;
    float* out_tome = out_mask + OUT_TOK;
    if (t < 192) ((float4*)out)[t] = ((const float4*)hidden)[t];   // row 0
    for (int i = t; i < OUT_TOK; i += 1024) out_mask[i] = 0.0f;
    if (t == 0) out_tome[0] = tome[0];

    s_cnt[i0] = 0; s_cnt[i1] = 0;
    __syncthreads();

    int dA = (int)(~(unsigned)g_best[i0]) & (M2 - 1);
    int dB = (int)(~(unsigned)g_best[i1]) & (M2 - 1);
    if (i0 >= 1) atomicAdd(&s_cnt[dA], 1);   // src row 0 is unmerged
    atomicAdd(&s_cnt[dB], 1);
    __syncthreads();

    int a = s_cnt[i0], b = s_cnt[i1];
    int pair = a + b;

    int v = pair;                            // inclusive warp scan
    #pragma unroll
    for (int o = 1; o < 32; o <<= 1) {
        int n = __shfl_up_sync(0xffffffffu, v, o);
        if (lane >= o) v += n;
    }
    if (lane == 31) s_wsum[wid] = v;
    __syncthreads();
    if (wid == 0) {
        int w = s_wsum[lane];
        #pragma unroll
        for (int o = 1; o < 32; o <<= 1) {
            int n = __shfl_up_sync(0xffffffffu, w, o);
            if (lane >= o) w += n;
        }
        s_wsum[lane] = w;
    }
    __syncthreads();
    int incl = v + ((wid > 0) ? s_wsum[wid - 1] : 0);
    int excl = incl - pair;

    s_off[i0] = excl;
    s_off[i1] = excl + a;
    g_cnt[i0] = a;  g_cnt[i1] = b;
    g_off[i0] = excl; g_off[i1] = excl + a;
    __syncthreads();

    s_cnt[i0] = s_off[i0]; s_cnt[i1] = s_off[i1];   // fill cursors
    __syncthreads();
    if (i0 >= 1) { int p = atomicAdd(&s_cnt[dA], 1); g_list[p] = i0; }
    {             int p = atomicAdd(&s_cnt[dB], 1); g_list[p] = i1; }
}

// ------------------------------------------------------------------------
// K4: gather-merge (best-measured design), uniform grid.
// Block j: out row 1+j = (dst_row + sum srcs)/(1+cnt).   grid: 2048 x 192
// ------------------------------------------------------------------------
__global__ __launch_bounds__(192) void k_merge(const float* __restrict__ hidden,
                                               const float* __restrict__ tome,
                                               float* __restrict__ out) {
    float* out_tok  = out;                              // 2049 x 768
    float* out_tome = out + (size_t)OUT_TOK * D_HID + OUT_TOK;
    int j = blockIdx.x, t = threadIdx.x;

    int cnt = g_cnt[j];
    int off = g_off[j];
    float inv = 1.0f / (1.0f + (float)cnt);

    float4 acc = ((const float4*)&hidden[(size_t)(2 * j + 1) * D_HID])[t];

    int s = 0;
    for (; s + 4 <= cnt; s += 4) {
        int i0 = g_list[off + s + 0];
        int i1 = g_list[off + s + 1];
        int i2 = g_list[off + s + 2];
        int i3 = g_list[off + s + 3];
        float4 v0 = ((const float4*)&hidden[(size_t)(2 * i0) * D_HID])[t];
        float4 v1 = ((const float4*)&hidden[(size_t)(2 * i1) * D_HID])[t];
        float4 v2 = ((const float4*)&hidden[(size_t)(2 * i2) * D_HID])[t];
        float4 v3 = ((const float4*)&hidden[(size_t)(2 * i3) * D_HID])[t];
        acc.x += v0.x + v1.x + v2.x + v3.x;
        acc.y += v0.y + v1.y + v2.y + v3.y;
        acc.z += v0.z + v1.z + v2.z + v3.z;
        acc.w += v0.w + v1.w + v2.w + v3.w;
    }
    for (; s < cnt; s++) {
        int i0 = g_list[off + s];
        float4 v0 = ((const float4*)&hidden[(size_t)(2 * i0) * D_HID])[t];
        acc.x += v0.x; acc.y += v0.y; acc.z += v0.z; acc.w += v0.w;
    }
    acc.x *= inv; acc.y *= inv; acc.z *= inv; acc.w *= inv;
    ((float4*)&out_tok[(size_t)(1 + j) * D_HID])[t] = acc;

    if (t == 0) {
        float ts = tome[2 * j + 1];
        for (int q = 0; q < cnt; q++) ts += tome[2 * g_list[off + q]];
        out_tome[1 + j] = ts;
    }
}

// ------------------------------------------------------------------------
extern "C" void kernel_launch(void* const* d_in, const int* in_sizes, int n_in,
                              void* d_out, int out_size) {
    const float* hidden = (const float*)d_in[0];
    const float* key    = (const float*)d_in[3];
    const float* tome   = (const float*)d_in[4];
    float* out = (float*)d_out;

    cudaFuncSetAttribute(k_argmax,
                         cudaFuncAttributeMaxDynamicSharedMemorySize, 65536);

    k_metric<<<512, 512>>>(key);
    k_argmax<<<dim3(M2 / BM, M2 / BM), 256, 65536>>>();
    k_build<<<1, 1024>>>(hidden, tome, out);
    k_merge<<<M2, 192>>>(hidden, tome, out);
}